// round 17
// baseline (speedup 1.0000x reference)
#include <cuda_runtime.h>
#include <math.h>

#define HEIGHT 1024
#define WIDTH  2048
#define PPT 4      // pixels per thread (4 | 2048, float4 aligned)
#define TPB 256    // R13/R14/R16 shape (best measured)

typedef unsigned long long ull;

// ---- f32x2 packed helpers (FFMA2 path; IEEE RN per lane) ----
__device__ __forceinline__ ull pk2(float lo, float hi) {
    ull r; asm("mov.b64 %0, {%1,%2};" : "=l"(r) : "f"(lo), "f"(hi)); return r;
}
__device__ __forceinline__ void upk2(float& lo, float& hi, ull v) {
    asm("mov.b64 {%0,%1}, %2;" : "=f"(lo), "=f"(hi) : "l"(v));
}
__device__ __forceinline__ ull fma2(ull a, ull b, ull c) {
    ull d; asm("fma.rn.f32x2 %0, %1, %2, %3;" : "=l"(d) : "l"(a), "l"(b), "l"(c)); return d;
}

// ---------------------------------------------------------------------------
// Compile-time trig tables (R13-exact float32 grid replication).
// phi tables stored DUPLICATED (each value twice) so one LDG.128 delivers two
// pre-broadcast (v,v) f32x2 pairs -- zero-cost lane broadcast for packing.
// ---------------------------------------------------------------------------
constexpr double PI_D = 3.141592653589793238462643383279502884;

constexpr double ksin0(double x) {
    const double x2 = x * x;
    double t = x, s = x;
    for (int k = 1; k <= 13; ++k) { t *= -x2 / (double)((2 * k) * (2 * k + 1)); s += t; }
    return s;
}
constexpr double kcos0(double x) {
    const double x2 = x * x;
    double t = 1.0, s = 1.0;
    for (int k = 1; k <= 13; ++k) { t *= -x2 / (double)((2 * k - 1) * (2 * k)); s += t; }
    return s;
}
constexpr double ksin(double x) {
    const double ax = x < 0 ? -x : x;
    const double s  = (ax > PI_D * 0.5) ? ksin0(PI_D - ax) : ksin0(ax);
    return x < 0 ? -s : s;
}
constexpr double kcos(double x) {
    const double ax = x < 0 ? -x : x;
    return (ax > PI_D * 0.5) ? -kcos0(PI_D - ax) : kcos0(ax);
}

struct Tables {
    alignas(16) float sth[HEIGHT];
    alignas(16) float cth[HEIGHT];
    alignas(16) float sph2[2 * WIDTH];   // duplicated: [2j] == [2j+1]
    alignas(16) float cph2[2 * WIDTH];
};

constexpr Tables make_tables() {
    Tables t{};
    for (int i = 0; i < HEIGHT; ++i) {
        const float gx = -1.0f + (float)i * (2.0f / (float)HEIGHT);   // exact
        const float pm = gx * 1.5707963267948966f;                    // fl32 mul
        const float th = pm + 1.5707963267948966f;                    // fl32 add
        t.sth[i] = (float)ksin((double)th);
        t.cth[i] = (float)kcos((double)th);
    }
    for (int j = 0; j < WIDTH; ++j) {
        const float gy = -1.0f + (float)j * (2.0f / (float)WIDTH);    // exact
        const float ph = gy * 3.14159265358979323846f;                // fl32 mul
        const float s = (float)ksin((double)ph);
        const float c = (float)kcos((double)ph);
        t.sph2[2 * j] = s; t.sph2[2 * j + 1] = s;
        t.cph2[2 * j] = c; t.cph2[2 * j + 1] = c;
    }
    return t;
}

__device__ constexpr Tables g_tables = make_tables();

// ---------------------------------------------------------------------------

__device__ __forceinline__ float fsqrt_approx(float x) {
    float r;
    asm("sqrt.approx.f32 %0, %1;" : "=f"(r) : "f"(x));
    return r;
}

__global__ void __launch_bounds__(TPB)
depth3dgrid_kernel(const float* __restrict__ depth,
                   const float* __restrict__ trans,
                   float* __restrict__ out)
{
    // Block-uniform geometry: each block = 1024 consecutive px = half a row.
    const int b  = blockIdx.y;
    const int hr = blockIdx.x >> 1;
    const int w0 = ((blockIdx.x & 1) << 10) + threadIdx.x * PPT;
    const int base = hr * WIDTH + w0;

    // Pre-scaled transform, once per block. Layout keeps (x,y)-channel pairs
    // 8B-adjacent so they load as single LDS.64 packed operands:
    // sC[0..3]=s_th*T0j, [4..7]=s_th*T1j, [8..11]=c_th*T2j, [12..15]=T3j
    __shared__ float sC[16];
    if (threadIdx.x < 16) {
        const float tv = trans[b * 16 + threadIdx.x];
        const int   r  = threadIdx.x >> 2;
        const float s_th = g_tables.sth[hr];
        const float c_th = g_tables.cth[hr];
        const float m = (r < 2) ? s_th : ((r == 2) ? c_th : 1.0f);
        sC[threadIdx.x] = tv * m;
    }
    __syncthreads();

    // Packed (x,y)-channel constants: zero duplication, direct LDS.64
    const ull A01  = *(const ull*)&sC[0];    // (a0, a1)
    const ull B01  = *(const ull*)&sC[4];    // (b0, b1)
    const ull K01  = *(const ull*)&sC[8];    // (k0, k1)
    const ull T301 = *(const ull*)&sC[12];   // (T30, T31)
    const float a2 = sC[2], b2 = sC[6], k2 = sC[10], T32 = sC[14];

    // Packed dual-poly coefficients: lane0 = acos P3 (in xa, 2/pi folded),
    // lane1 = atan P7 (in ss, 1/pi folded). Same values as R16.
    const ull C3 = pk2(-0.0119235f, -0.01241185f);
    const ull C2 = pk2( 0.0472755f,  0.04655499f);
    const ull C1 = pk2(-0.1350346f, -0.10222863f);
    const ull C0 = pk2( 0.9999573f,  0.31806159f);

    // Duplicated phi tables: one LDG.128 = two (v,v) broadcast pairs
    const ulonglong2 cq0 = *(const ulonglong2*)&g_tables.cph2[2 * w0];
    const ulonglong2 cq1 = *(const ulonglong2*)&g_tables.cph2[2 * w0 + 4];
    const ulonglong2 sq0 = *(const ulonglong2*)&g_tables.sph2[2 * w0];
    const ulonglong2 sq1 = *(const ulonglong2*)&g_tables.sph2[2 * w0 + 4];
    const float4 dv = *(const float4*)(depth + (size_t)b * (HEIGHT * WIDTH) + base);

    const ull CP2s[4] = {cq0.x, cq0.y, cq1.x, cq1.y};
    const ull SP2s[4] = {sq0.x, sq0.y, sq1.x, sq1.y};
    const float dd[4] = {dv.x, dv.y, dv.z, dv.w};

    float res[8];
#pragma unroll
    for (int k = 0; k < 4; ++k) {
        const ull CP2 = CP2s[k], SP2 = SP2s[k];
        const float d = dd[k];
        const ull D2 = pk2(d, d);
        float cp, sp, dummy0, dummy1;
        upk2(cp, dummy0, CP2);
        upk2(sp, dummy1, SP2);

        // packed (px,py) transform -- per-lane IEEE RN == R16's scalar fmaf
        const ull PXY = fma2(D2, fma2(CP2, A01, fma2(SP2, B01, K01)), T301);
        const float pz = fmaf(d, fmaf(cp, a2, fmaf(sp, b2, k2)), T32);
        float px, py;
        upk2(px, py, PXY);

        // t = pz / (sqrt(s2) + 1e-4) via rsqrt + first-order expansion
        const float s2  = fmaf(px, px, fmaf(py, py, fmaf(pz, pz, 1e-30f)));
        const float ris = rsqrtf(s2);
        const float pr  = pz * ris;
        const float t   = fmaf(pr * ris, -1e-4f, pr);

        // poly inputs: lane0 xa (acos), lane1 ss (atan)
        const float xa = fabsf(t);
        const float ax = fabsf(px), ay = fabsf(py);
        const float mx = fmaxf(fmaxf(ax, ay), 1e-37f);
        const float mn = fminf(ax, ay);
        const float a  = __fdividef(mn, mx);
        const float ss = a * a;

        ull V = pk2(xa, ss);
        ull W = fma2(V, C3, C2);
        W = fma2(W, V, C1);
        W = fma2(W, V, C0);
        float p, q;
        upk2(p, q, W);

        // theta = acos(t)*2/pi - 1; sign via XOR (R16-identical)
        const float sq = fsqrt_approx(fmaxf(1.0f - xa, 1e-30f));
        const float v  = fmaf(p, sq, -1.0f);
        const float theta_o = __int_as_float(__float_as_int(v) ^
                                 (__float_as_int(t) & 0x80000000));

        // phi: quadrant fixes 0.5-q / 1-q (R16-identical select structure)
        q = q * a;                                     // atan(mn/mx)/pi
        q = (ay > ax)   ? (0.5f - q) : q;
        q = (px < 0.0f) ? (1.0f - q) : q;
        const float phi_o = copysignf(q, py);

        res[2 * k]     = phi_o;    // channel 0 = phi
        res[2 * k + 1] = theta_o;  // channel 1 = theta
    }

    float4* optr = (float4*)(out + ((size_t)b * (HEIGHT * WIDTH) + base) * 2);
    optr[0] = make_float4(res[0], res[1], res[2], res[3]);
    optr[1] = make_float4(res[4], res[5], res[6], res[7]);
}

extern "C" void kernel_launch(void* const* d_in, const int* in_sizes, int n_in,
                              void* d_out, int out_size)
{
    const float* depth = (const float*)d_in[0];   // (4,1024,2048,1) f32
    const float* trans = (const float*)d_in[1];   // (4,4,4) f32
    float* out = (float*)d_out;                   // (4,1024,2048,2) f32

    dim3 grid(HEIGHT * 2, 4, 1);                  // (2048, 4)
    depth3dgrid_kernel<<<grid, TPB>>>(depth, trans, out);
}